// round 2
// baseline (speedup 1.0000x reference)
#include <cuda_runtime.h>
#include <math.h>

#define B    64
#define T    4096
#define DIM  256
#define NLOC 32
#define KS   31
#define PAD  15
#define TPB  512            // t-range handled per block in the main kernel
#define NCH  (T / TPB)      // 8 chunks per batch
#define CH   8              // t's processed per inner iteration (== warps/block)

// -------- scratch (static device globals; no allocation allowed) ----------
__device__ float g_u[B * DIM];            // W^T q per batch
__device__ float g_g[B * KS];             // collapsed conv kernel per batch
__device__ float g_cb[B];                 // collapsed conv bias per batch
__device__ float g_energ[B * T];          // raw energies
__device__ float g_pm[B * NCH];           // per-chunk running max
__device__ float g_ps[B * NCH];           // per-chunk exp-sum
__device__ float g_pctx[B * NCH * DIM];   // per-chunk unnormalized context
__device__ float g_M[B];                  // final max per batch
__device__ float g_S[B];                  // final softmax denom per batch

// ---------------------------------------------------------------------------
// Kernel A: tiny prep. u_b = W^T q_b ; v_b = L^T q_b ; g_b[k] = conv_w^T v_b ;
//           c_b = conv_b · v_b.   One block per batch.
// ---------------------------------------------------------------------------
__global__ void prep_kernel(const float* __restrict__ q,
                            const float* __restrict__ Ww,
                            const float* __restrict__ Lw,
                            const float* __restrict__ convw,
                            const float* __restrict__ convb) {
    __shared__ float sq[DIM];
    __shared__ float sv[NLOC];
    const int b = blockIdx.x;
    const int tid = threadIdx.x;

    sq[tid] = q[b * DIM + tid];
    __syncthreads();

    // u[d] = sum_e W[e,d] * q[e]   (W row-major [e*DIM + d]; coalesced over d)
    float u = 0.f;
#pragma unroll 8
    for (int e = 0; e < DIM; e++) u = fmaf(Ww[e * DIM + tid], sq[e], u);
    g_u[b * DIM + tid] = u;

    if (tid < NLOC) {
        float v = 0.f;
        for (int e = 0; e < DIM; e++) v = fmaf(Lw[e * NLOC + tid], sq[e], v);
        sv[tid] = v;
    }
    __syncthreads();

    if (tid < KS) {
        float gg = 0.f;
        for (int c = 0; c < NLOC; c++) gg = fmaf(convw[c * KS + tid], sv[c], gg);
        g_g[b * KS + tid] = gg;
    }
    if (tid == 0) {
        float cb = 0.f;
        for (int c = 0; c < NLOC; c++) cb = fmaf(convb[c], sv[c], cb);
        g_cb[b] = cb;
    }
}

// ---------------------------------------------------------------------------
// Kernel B: the HBM-bound pass. Each block = (batch b, t-chunk ch).
// Single read of encoder_out serves BOTH the energy dot-product and the
// online-softmax context accumulation (flash-style).
// ---------------------------------------------------------------------------
__global__ void __launch_bounds__(256)
energy_ctx_kernel(const float* __restrict__ enc,
                  const float* __restrict__ mask) {
    __shared__ float su[DIM];
    __shared__ float sg[KS];
    __shared__ float scb;
    __shared__ float smask[TPB + 2 * PAD];
    __shared__ __align__(16) float tile[CH][DIM];   // 16B-aligned: float4 stores
    __shared__ float earr[CH];

    const int b   = blockIdx.x;
    const int ch  = blockIdx.y;
    const int tid = threadIdx.x;
    const int w   = tid >> 5;
    const int l   = tid & 31;
    const int t0  = ch * TPB;

    su[tid] = g_u[b * DIM + tid];
    if (tid < KS) sg[tid] = g_g[b * KS + tid];
    if (tid == 0) scb = g_cb[b];
    for (int j = tid; j < TPB + 2 * PAD; j += 256) {
        int gt = t0 - PAD + j;
        smask[j] = (gt >= 0 && gt < T) ? mask[b * T + gt] : 0.f;
    }
    __syncthreads();

    float m   = -INFINITY;   // running max (per block, replicated per thread)
    float s   = 0.f;         // running exp-sum (replicated)
    float ctx = 0.f;         // this thread owns output dim `tid`

    for (int it = 0; it < TPB / CH; it++) {
        const int tloc = it * CH + w;
        const int t    = t0 + tloc;
        const float* row = enc + ((size_t)t * B + b) * DIM;

        // warp w loads full 256-float row of encoder_out (lane l: dims 8l..8l+7)
        float4 v0 = *(const float4*)(row + l * 8);
        float4 v1 = *(const float4*)(row + l * 8 + 4);
        *(float4*)(&tile[w][l * 8])     = v0;
        *(float4*)(&tile[w][l * 8 + 4]) = v1;

        float p = v0.x * su[l * 8]     + v0.y * su[l * 8 + 1]
                + v0.z * su[l * 8 + 2] + v0.w * su[l * 8 + 3]
                + v1.x * su[l * 8 + 4] + v1.y * su[l * 8 + 5]
                + v1.z * su[l * 8 + 6] + v1.w * su[l * 8 + 7];
        // location term folded into the same warp reduction (lane k -> tap k)
        if (l < KS) p = fmaf(sg[l], smask[tloc + l], p);

#pragma unroll
        for (int off = 16; off > 0; off >>= 1)
            p += __shfl_down_sync(0xffffffffu, p, off);

        if (l == 0) {
            p += scb;
            earr[w] = p;
            g_energ[b * T + t] = p;     // cached for the attn epilogue
        }
        __syncthreads();

        // online softmax update (all threads redundantly track m, s)
        float cm = earr[0];
#pragma unroll
        for (int k = 1; k < CH; k++) cm = fmaxf(cm, earr[k]);
        float newm  = fmaxf(m, cm);
        float scale = __expf(m - newm);  // exp(-inf) == 0 handles first iter
        s   *= scale;
        ctx *= scale;
#pragma unroll
        for (int k = 0; k < CH; k++) {
            float pk = __expf(earr[k] - newm);
            s += pk;
            ctx = fmaf(pk, tile[k][tid], ctx);
        }
        m = newm;
        __syncthreads();   // protect tile/earr before next iteration overwrite
    }

    const int pidx = b * NCH + ch;
    g_pctx[pidx * DIM + tid] = ctx;
    if (tid == 0) { g_pm[pidx] = m; g_ps[pidx] = s; }
}

// ---------------------------------------------------------------------------
// Kernel C: combine per-chunk partials, write context = (L=1, B, DIM).
// ---------------------------------------------------------------------------
__global__ void combine_kernel(float* __restrict__ out) {
    __shared__ float sm[NCH], ss[NCH];
    const int b = blockIdx.x, tid = threadIdx.x;
    if (tid < NCH) { sm[tid] = g_pm[b * NCH + tid]; ss[tid] = g_ps[b * NCH + tid]; }
    __syncthreads();

    float M = sm[0];
#pragma unroll
    for (int j = 1; j < NCH; j++) M = fmaxf(M, sm[j]);
    float sc[NCH];
    float S = 0.f;
#pragma unroll
    for (int j = 0; j < NCH; j++) { sc[j] = __expf(sm[j] - M); S = fmaf(ss[j], sc[j], S); }

    float ctx = 0.f;
#pragma unroll
    for (int j = 0; j < NCH; j++)
        ctx = fmaf(g_pctx[(b * NCH + j) * DIM + tid], sc[j], ctx);

    out[b * DIM + tid] = ctx / S;
    if (tid == 0) { g_M[b] = M; g_S[b] = S; }
}

// ---------------------------------------------------------------------------
// Kernel D: attn[b,t,0] = exp(e - M_b) / S_b   (reads 1 MB energy scratch)
// ---------------------------------------------------------------------------
__global__ void attn_kernel(float* __restrict__ out) {
    const int i = blockIdx.x * blockDim.x + threadIdx.x;  // over B*T
    const int b = i >> 12;                                // T = 4096
    out[(size_t)(B * DIM) + i] = __expf(g_energ[i] - g_M[b]) * (1.0f / g_S[b]);
}

// ---------------------------------------------------------------------------
extern "C" void kernel_launch(void* const* d_in, const int* in_sizes, int n_in,
                              void* d_out, int out_size) {
    const float* q     = (const float*)d_in[0];  // (1,64,256)
    const float* enc   = (const float*)d_in[1];  // (4096,64,256)
    const float* mask  = (const float*)d_in[2];  // (64,4096,1)
    const float* Ww    = (const float*)d_in[3];  // (256,256)
    const float* Lw    = (const float*)d_in[4];  // (256,32)
    const float* convw = (const float*)d_in[5];  // (32,1,31)
    const float* convb = (const float*)d_in[6];  // (32,)
    float* out = (float*)d_out;                  // context(16384) ++ attn(262144)

    prep_kernel<<<B, 256>>>(q, Ww, Lw, convw, convb);
    dim3 gridB(B, NCH);
    energy_ctx_kernel<<<gridB, 256>>>(enc, mask);
    combine_kernel<<<B, DIM>>>(out);
    attn_kernel<<<(B * T) / 256, 256>>>(out);
}

// round 3
// speedup vs baseline: 1.2036x; 1.2036x over previous
#include <cuda_runtime.h>
#include <math.h>

#define B    64
#define T    4096
#define DIM  256
#define NLOC 32
#define KS   31
#define PAD  15
#define TPB  256            // t-range handled per block in the main kernel
#define NCH  (T / TPB)      // 16 chunks per batch -> 1024 blocks
#define CH   8              // t's processed per inner iteration (== warps/block)
#define NITER (TPB / CH)    // 32

// -------- scratch (static device globals; no allocation allowed) ----------
__device__ float g_u[B * DIM];            // W^T q per batch
__device__ float g_g[B * KS];             // collapsed conv kernel per batch
__device__ float g_cb[B];                 // collapsed conv bias per batch
__device__ float g_energ[B * T];          // raw energies
__device__ float g_pm[B * NCH];           // per-chunk running max
__device__ float g_ps[B * NCH];           // per-chunk exp-sum
__device__ float g_pctx[B * NCH * DIM];   // per-chunk unnormalized context
__device__ float g_M[B];                  // final max per batch
__device__ float g_invS[B];               // final 1/denominator per batch

// ---------------------------------------------------------------------------
// Kernel A: tiny prep. u_b = W^T q_b ; v_b = L^T q_b ; g_b[k] = conv_w^T v_b ;
//           c_b = conv_b · v_b.   One block per batch.
// ---------------------------------------------------------------------------
__global__ void prep_kernel(const float* __restrict__ q,
                            const float* __restrict__ Ww,
                            const float* __restrict__ Lw,
                            const float* __restrict__ convw,
                            const float* __restrict__ convb) {
    __shared__ float sq[DIM];
    __shared__ float sv[NLOC];
    const int b = blockIdx.x;
    const int tid = threadIdx.x;

    sq[tid] = q[b * DIM + tid];
    __syncthreads();

    float u = 0.f;
#pragma unroll 8
    for (int e = 0; e < DIM; e++) u = fmaf(Ww[e * DIM + tid], sq[e], u);
    g_u[b * DIM + tid] = u;

    if (tid < NLOC) {
        float v = 0.f;
        for (int e = 0; e < DIM; e++) v = fmaf(Lw[e * NLOC + tid], sq[e], v);
        sv[tid] = v;
    }
    __syncthreads();

    if (tid < KS) {
        float gg = 0.f;
        for (int c = 0; c < NLOC; c++) gg = fmaf(convw[c * KS + tid], sv[c], gg);
        g_g[b * KS + tid] = gg;
    }
    if (tid == 0) {
        float cb = 0.f;
        for (int c = 0; c < NLOC; c++) cb = fmaf(convb[c], sv[c], cb);
        g_cb[b] = cb;
    }
}

// ---------------------------------------------------------------------------
// Kernel B: the HBM-bound pass. Each block = (batch b, t-chunk ch).
// Single read of encoder_out serves BOTH the energy dot-product and the
// online-softmax context accumulation. Ping-pong tile buffers -> 1 barrier
// per iteration; next iteration's loads prefetched into registers; row exps
// computed once per warp (lanes 0..7) and broadcast via shuffles.
// ---------------------------------------------------------------------------
__global__ void __launch_bounds__(256)
energy_ctx_kernel(const float* __restrict__ enc,
                  const float* __restrict__ mask) {
    __shared__ float su[DIM];
    __shared__ float sg[KS];
    __shared__ float scb;
    __shared__ float smask[TPB + 2 * PAD];
    __shared__ __align__(16) float tile[2][CH][DIM];
    __shared__ float earr[2][CH];

    const int b   = blockIdx.x;
    const int ch  = blockIdx.y;
    const int tid = threadIdx.x;
    const int w   = tid >> 5;
    const int l   = tid & 31;
    const int t0  = ch * TPB;

    su[tid] = g_u[b * DIM + tid];
    if (tid < KS) sg[tid] = g_g[b * KS + tid];
    if (tid == 0) scb = g_cb[b];
    for (int j = tid; j < TPB + 2 * PAD; j += 256) {
        int gt = t0 - PAD + j;
        smask[j] = (gt >= 0 && gt < T) ? mask[b * T + gt] : 0.f;
    }
    __syncthreads();

    float m   = -INFINITY;   // running max (replicated per thread)
    float s   = 0.f;         // running exp-sum (replicated)
    float ctx = 0.f;         // this thread owns output dim `tid`

    // prefetch iteration 0
    const float* row0 = enc + ((size_t)(t0 + w) * B + b) * DIM;
    float4 v0 = *(const float4*)(row0 + l * 8);
    float4 v1 = *(const float4*)(row0 + l * 8 + 4);

    for (int it = 0; it < NITER; it++) {
        const int buf  = it & 1;
        const int tloc = it * CH + w;
        const float4 c0 = v0, c1 = v1;

        // prefetch next iteration's row while we process this one
        if (it + 1 < NITER) {
            const float* rp = enc + ((size_t)(t0 + (it + 1) * CH + w) * B + b) * DIM;
            v0 = *(const float4*)(rp + l * 8);
            v1 = *(const float4*)(rp + l * 8 + 4);
        }

        *(float4*)(&tile[buf][w][l * 8])     = c0;
        *(float4*)(&tile[buf][w][l * 8 + 4]) = c1;

        float p = c0.x * su[l * 8]     + c0.y * su[l * 8 + 1]
                + c0.z * su[l * 8 + 2] + c0.w * su[l * 8 + 3]
                + c1.x * su[l * 8 + 4] + c1.y * su[l * 8 + 5]
                + c1.z * su[l * 8 + 6] + c1.w * su[l * 8 + 7];
        if (l < KS) p = fmaf(sg[l], smask[tloc + l], p);

#pragma unroll
        for (int off = 16; off > 0; off >>= 1)
            p += __shfl_down_sync(0xffffffffu, p, off);

        if (l == 0) {
            p += scb;
            earr[buf][w] = p;
            g_energ[b * T + t0 + tloc] = p;   // cached for the attn epilogue
        }
        __syncthreads();

        // --- online softmax update, de-duplicated exps ---
        float cm = earr[buf][0];
#pragma unroll
        for (int k = 1; k < CH; k++) cm = fmaxf(cm, earr[buf][k]);
        if (cm > m) {                    // rescale only when max moves
            float sc = __expf(m - cm);   // exp(-inf)=0 handles first iter
            s *= sc; ctx *= sc; m = cm;
        }
        // lanes 0..7 each compute one row-exp; broadcast via shuffle
        float pv = (l < CH) ? __expf(earr[buf][l] - m) : 0.f;
        float ssum = 0.f;
#pragma unroll
        for (int k = 0; k < CH; k++) {
            float pk = __shfl_sync(0xffffffffu, pv, k);
            ssum += pk;
            ctx = fmaf(pk, tile[buf][k][tid], ctx);
        }
        s += ssum;
        // no second barrier: next iter writes the other buffer
    }

    const int pidx = b * NCH + ch;
    g_pctx[pidx * DIM + tid] = ctx;
    if (tid == 0) { g_pm[pidx] = m; g_ps[pidx] = s; }
}

// ---------------------------------------------------------------------------
// Kernel C: combine per-chunk partials, write context = (L=1, B, DIM).
// ---------------------------------------------------------------------------
__global__ void combine_kernel(float* __restrict__ out) {
    __shared__ float sm[NCH], ss[NCH];
    const int b = blockIdx.x, tid = threadIdx.x;
    if (tid < NCH) { sm[tid] = g_pm[b * NCH + tid]; ss[tid] = g_ps[b * NCH + tid]; }
    __syncthreads();

    float M = sm[0];
#pragma unroll
    for (int j = 1; j < NCH; j++) M = fmaxf(M, sm[j]);
    float sc[NCH];
    float S = 0.f;
#pragma unroll
    for (int j = 0; j < NCH; j++) { sc[j] = __expf(sm[j] - M); S = fmaf(ss[j], sc[j], S); }

    float ctx = 0.f;
#pragma unroll
    for (int j = 0; j < NCH; j++)
        ctx = fmaf(g_pctx[(b * NCH + j) * DIM + tid], sc[j], ctx);

    float invS = 1.0f / S;
    out[b * DIM + tid] = ctx * invS;
    if (tid == 0) { g_M[b] = M; g_invS[b] = invS; }
}

// ---------------------------------------------------------------------------
// Kernel D: attn[b,t,0] = exp(e - M_b) / S_b   (float4-vectorized)
// ---------------------------------------------------------------------------
__global__ void attn_kernel(float* __restrict__ out) {
    const int i = blockIdx.x * blockDim.x + threadIdx.x;  // over B*T/4
    const int b = i >> 10;                                // 1024 float4 per batch
    const float M = g_M[b];
    const float inv = g_invS[b];
    float4 e = ((const float4*)g_energ)[i];
    float4 r;
    r.x = __expf(e.x - M) * inv;
    r.y = __expf(e.y - M) * inv;
    r.z = __expf(e.z - M) * inv;
    r.w = __expf(e.w - M) * inv;
    ((float4*)(out + (size_t)B * DIM))[i] = r;
}

// ---------------------------------------------------------------------------
extern "C" void kernel_launch(void* const* d_in, const int* in_sizes, int n_in,
                              void* d_out, int out_size) {
    const float* q     = (const float*)d_in[0];  // (1,64,256)
    const float* enc   = (const float*)d_in[1];  // (4096,64,256)
    const float* mask  = (const float*)d_in[2];  // (64,4096,1)
    const float* Ww    = (const float*)d_in[3];  // (256,256)
    const float* Lw    = (const float*)d_in[4];  // (256,32)
    const float* convw = (const float*)d_in[5];  // (32,1,31)
    const float* convb = (const float*)d_in[6];  // (32,)
    float* out = (float*)d_out;                  // context(16384) ++ attn(262144)

    prep_kernel<<<B, 256>>>(q, Ww, Lw, convw, convb);
    dim3 gridB(B, NCH);
    energy_ctx_kernel<<<gridB, 256>>>(enc, mask);
    combine_kernel<<<B, DIM>>>(out);
    attn_kernel<<<(B * T / 4) / 256, 256>>>(out);
}

// round 4
// speedup vs baseline: 1.5878x; 1.3191x over previous
#include <cuda_runtime.h>
#include <math.h>

#define B    64
#define T    4096
#define DIM  256
#define NLOC 32
#define KS   31
#define PAD  15
#define TPW  32             // rows per warp
#define WPB  8              // warps per block
#define TPB  (TPW * WPB)    // 256 t per block
#define NCH  (T / TPB)      // 16 chunks per batch -> 1024 blocks

// -------- scratch (static device globals; no allocation allowed) ----------
__device__ float g_u[B * DIM];            // W^T q per batch
__device__ float g_g[B * KS];             // collapsed conv kernel per batch
__device__ float g_cb[B];                 // collapsed conv bias per batch
__device__ float g_energ[B * T];          // raw energies
__device__ float g_pm[B * NCH];           // per-block running max
__device__ float g_ps[B * NCH];           // per-block exp-sum
__device__ float g_pctx[B * NCH * DIM];   // per-block unnormalized context
__device__ float g_M[B];                  // final max per batch
__device__ float g_invS[B];               // final 1/denominator per batch

// ---------------------------------------------------------------------------
// Kernel A: tiny prep. u_b = W^T q_b ; v_b = L^T q_b ; g_b[k] = conv_w^T v_b ;
//           c_b = conv_b · v_b.   One block per batch.
// ---------------------------------------------------------------------------
__global__ void prep_kernel(const float* __restrict__ q,
                            const float* __restrict__ Ww,
                            const float* __restrict__ Lw,
                            const float* __restrict__ convw,
                            const float* __restrict__ convb) {
    __shared__ float sq[DIM];
    __shared__ float sv[NLOC];
    const int b = blockIdx.x;
    const int tid = threadIdx.x;

    sq[tid] = q[b * DIM + tid];
    __syncthreads();

    float u = 0.f;
#pragma unroll 8
    for (int e = 0; e < DIM; e++) u = fmaf(Ww[e * DIM + tid], sq[e], u);
    g_u[b * DIM + tid] = u;

    if (tid < NLOC) {
        float v = 0.f;
        for (int e = 0; e < DIM; e++) v = fmaf(Lw[e * NLOC + tid], sq[e], v);
        sv[tid] = v;
    }
    __syncthreads();

    if (tid < KS) {
        float gg = 0.f;
        for (int c = 0; c < NLOC; c++) gg = fmaf(convw[c * KS + tid], sv[c], gg);
        g_g[b * KS + tid] = gg;
    }
    if (tid == 0) {
        float cb = 0.f;
        for (int c = 0; c < NLOC; c++) cb = fmaf(convb[c], sv[c], cb);
        g_cb[b] = cb;
    }
}

// ---------------------------------------------------------------------------
// Kernel B: HBM-bound pass, fully warp-autonomous hot loop.
// Each warp owns 32 consecutive t's; lane l owns output dims [8l, 8l+8).
// No shared memory / barriers inside the loop; one epilogue barrier merges
// the 8 warp partials of the block.
// ---------------------------------------------------------------------------
__global__ void __launch_bounds__(256)
energy_ctx_kernel(const float* __restrict__ enc,
                  const float* __restrict__ mask) {
    __shared__ float smask[TPB + 2 * PAD];
    __shared__ float red_m[WPB], red_s[WPB];
    __shared__ __align__(16) float red_ctx[WPB][DIM];

    const int b   = blockIdx.x;
    const int ch  = blockIdx.y;
    const int tid = threadIdx.x;
    const int w   = tid >> 5;
    const int l   = tid & 31;
    const int t0  = ch * TPB;

    // register-resident slices
    const float4 uA = *(const float4*)(g_u + b * DIM + l * 8);
    const float4 uB = *(const float4*)(g_u + b * DIM + l * 8 + 4);
    const float  gl = (l < KS) ? g_g[b * KS + l] : 0.f;
    const float  cb = g_cb[b];

    for (int j = tid; j < TPB + 2 * PAD; j += 256) {
        int gt = t0 - PAD + j;
        smask[j] = (gt >= 0 && gt < T) ? mask[b * T + gt] : 0.f;
    }
    __syncthreads();

    const int tw0 = t0 + w * TPW;            // warp's first t
    float m = -INFINITY, s = 0.f;
    float cx[8] = {0.f, 0.f, 0.f, 0.f, 0.f, 0.f, 0.f, 0.f};

    const float* rowp = enc + ((size_t)tw0 * B + b) * DIM + l * 8;
    float4 v0 = *(const float4*)rowp;
    float4 v1 = *(const float4*)(rowp + 4);

    for (int i = 0; i < TPW; i++) {
        const float4 a0 = v0, a1 = v1;
        if (i + 1 < TPW) {
            rowp += (size_t)B * DIM;
            v0 = *(const float4*)rowp;
            v1 = *(const float4*)(rowp + 4);
        }
        const float msk = (l < KS) ? smask[w * TPW + i + l] : 0.f;

        float p;
        p = a0.x * uA.x;
        p = fmaf(a0.y, uA.y, p);
        p = fmaf(a0.z, uA.z, p);
        p = fmaf(a0.w, uA.w, p);
        p = fmaf(a1.x, uB.x, p);
        p = fmaf(a1.y, uB.y, p);
        p = fmaf(a1.z, uB.z, p);
        p = fmaf(a1.w, uB.w, p);
        p = fmaf(gl, msk, p);

#pragma unroll
        for (int off = 16; off > 0; off >>= 1)
            p += __shfl_xor_sync(0xffffffffu, p, off);
        p += cb;                              // uniform across warp

        if (l == 0) g_energ[b * T + tw0 + i] = p;

        if (p > m) {                          // warp-uniform branch
            const float sc = __expf(m - p);   // exp(-inf)=0 handles first row
            s = fmaf(s, sc, 1.f);
#pragma unroll
            for (int j = 0; j < 8; j++) cx[j] *= sc;
            m = p;
            cx[0] = fmaf(1.f, a0.x, cx[0]); cx[1] = fmaf(1.f, a0.y, cx[1]);
            cx[2] = fmaf(1.f, a0.z, cx[2]); cx[3] = fmaf(1.f, a0.w, cx[3]);
            cx[4] = fmaf(1.f, a1.x, cx[4]); cx[5] = fmaf(1.f, a1.y, cx[5]);
            cx[6] = fmaf(1.f, a1.z, cx[6]); cx[7] = fmaf(1.f, a1.w, cx[7]);
        } else {
            const float pe = __expf(p - m);
            s += pe;
            cx[0] = fmaf(pe, a0.x, cx[0]); cx[1] = fmaf(pe, a0.y, cx[1]);
            cx[2] = fmaf(pe, a0.z, cx[2]); cx[3] = fmaf(pe, a0.w, cx[3]);
            cx[4] = fmaf(pe, a1.x, cx[4]); cx[5] = fmaf(pe, a1.y, cx[5]);
            cx[6] = fmaf(pe, a1.z, cx[6]); cx[7] = fmaf(pe, a1.w, cx[7]);
        }
    }

    // ---- block epilogue: merge 8 warp partials ----
    if (l == 0) { red_m[w] = m; red_s[w] = s; }
    *(float4*)(&red_ctx[w][l * 8])     = *(float4*)(&cx[0]);
    *(float4*)(&red_ctx[w][l * 8 + 4]) = *(float4*)(&cx[4]);
    __syncthreads();

    float M = red_m[0];
#pragma unroll
    for (int j = 1; j < WPB; j++) M = fmaxf(M, red_m[j]);
    float S = 0.f, C = 0.f;
#pragma unroll
    for (int j = 0; j < WPB; j++) {
        const float wj = __expf(red_m[j] - M);
        S = fmaf(red_s[j], wj, S);
        C = fmaf(wj, red_ctx[j][tid], C);
    }

    const int pidx = b * NCH + ch;
    g_pctx[pidx * DIM + tid] = C;
    if (tid == 0) { g_pm[pidx] = M; g_ps[pidx] = S; }
}

// ---------------------------------------------------------------------------
// Kernel C: combine per-chunk partials, write context = (L=1, B, DIM).
// ---------------------------------------------------------------------------
__global__ void combine_kernel(float* __restrict__ out) {
    __shared__ float sm[NCH], ss[NCH];
    const int b = blockIdx.x, tid = threadIdx.x;
    if (tid < NCH) { sm[tid] = g_pm[b * NCH + tid]; ss[tid] = g_ps[b * NCH + tid]; }
    __syncthreads();

    float M = sm[0];
#pragma unroll
    for (int j = 1; j < NCH; j++) M = fmaxf(M, sm[j]);
    float sc[NCH];
    float S = 0.f;
#pragma unroll
    for (int j = 0; j < NCH; j++) { sc[j] = __expf(sm[j] - M); S = fmaf(ss[j], sc[j], S); }

    float ctx = 0.f;
#pragma unroll
    for (int j = 0; j < NCH; j++)
        ctx = fmaf(g_pctx[(b * NCH + j) * DIM + tid], sc[j], ctx);

    const float invS = 1.0f / S;
    out[b * DIM + tid] = ctx * invS;
    if (tid == 0) { g_M[b] = M; g_invS[b] = invS; }
}

// ---------------------------------------------------------------------------
// Kernel D: attn[b,t,0] = exp(e - M_b) * invS_b   (float4-vectorized)
// ---------------------------------------------------------------------------
__global__ void attn_kernel(float* __restrict__ out) {
    const int i = blockIdx.x * blockDim.x + threadIdx.x;  // over B*T/4
    const int b = i >> 10;                                // 1024 float4 per batch
    const float M = g_M[b];
    const float inv = g_invS[b];
    float4 e = ((const float4*)g_energ)[i];
    float4 r;
    r.x = __expf(e.x - M) * inv;
    r.y = __expf(e.y - M) * inv;
    r.z = __expf(e.z - M) * inv;
    r.w = __expf(e.w - M) * inv;
    ((float4*)(out + (size_t)B * DIM))[i] = r;
}

// ---------------------------------------------------------------------------
extern "C" void kernel_launch(void* const* d_in, const int* in_sizes, int n_in,
                              void* d_out, int out_size) {
    const float* q     = (const float*)d_in[0];  // (1,64,256)
    const float* enc   = (const float*)d_in[1];  // (4096,64,256)
    const float* mask  = (const float*)d_in[2];  // (64,4096,1)
    const float* Ww    = (const float*)d_in[3];  // (256,256)
    const float* Lw    = (const float*)d_in[4];  // (256,32)
    const float* convw = (const float*)d_in[5];  // (32,1,31)
    const float* convb = (const float*)d_in[6];  // (32,)
    float* out = (float*)d_out;                  // context(16384) ++ attn(262144)

    prep_kernel<<<B, 256>>>(q, Ww, Lw, convw, convb);
    dim3 gridB(B, NCH);
    energy_ctx_kernel<<<gridB, 256>>>(enc, mask);
    combine_kernel<<<B, DIM>>>(out);
    attn_kernel<<<(B * T / 4) / 256, 256>>>(out);
}

// round 5
// speedup vs baseline: 1.7071x; 1.0752x over previous
#include <cuda_runtime.h>
#include <math.h>

#define B    64
#define T    4096
#define DIM  256
#define NLOC 32
#define KS   31
#define PAD  15
#define TPW  32             // rows per warp
#define WPB  8              // warps per block
#define TPB  (TPW * WPB)    // 256 t per block
#define NCH  (T / TPB)      // 16 chunks per batch -> 1024 blocks

// -------- scratch (static device globals; no allocation allowed) ----------
__device__ float g_u[B * DIM];            // W^T q per batch
__device__ float g_g[B * KS];             // collapsed conv kernel per batch
__device__ float g_cb[B];                 // collapsed conv bias per batch
__device__ float g_energ[B * T];          // raw energies
__device__ float g_pm[B * NCH];           // per-block running max
__device__ float g_ps[B * NCH];           // per-block exp-sum
__device__ float g_pctx[B * NCH * DIM];   // per-block unnormalized context

// ---------------------------------------------------------------------------
// Kernel A: tiny prep. u_b = W^T q_b ; v_b = L^T q_b ; g_b[k] = conv_w^T v_b ;
//           c_b = conv_b · v_b.   One block per batch.
// ---------------------------------------------------------------------------
__global__ void prep_kernel(const float* __restrict__ q,
                            const float* __restrict__ Ww,
                            const float* __restrict__ Lw,
                            const float* __restrict__ convw,
                            const float* __restrict__ convb) {
    __shared__ float sq[DIM];
    __shared__ float sv[NLOC];
    const int b = blockIdx.x;
    const int tid = threadIdx.x;

    sq[tid] = q[b * DIM + tid];
    __syncthreads();

    float u = 0.f;
#pragma unroll 8
    for (int e = 0; e < DIM; e++) u = fmaf(Ww[e * DIM + tid], sq[e], u);
    g_u[b * DIM + tid] = u;

    if (tid < NLOC) {
        float v = 0.f;
        for (int e = 0; e < DIM; e++) v = fmaf(Lw[e * NLOC + tid], sq[e], v);
        sv[tid] = v;
    }
    __syncthreads();

    if (tid < KS) {
        float gg = 0.f;
        for (int c = 0; c < NLOC; c++) gg = fmaf(convw[c * KS + tid], sv[c], gg);
        g_g[b * KS + tid] = gg;
    }
    if (tid == 0) {
        float cb = 0.f;
        for (int c = 0; c < NLOC; c++) cb = fmaf(convb[c], sv[c], cb);
        g_cb[b] = cb;
    }
}

// ---------------------------------------------------------------------------
// Kernel B: HBM-bound pass, warp-autonomous hot loop, prefetch depth 2
// (4 LDG.128 in flight per warp -> ~16KB/SM outstanding, Little's-law OK).
// Each warp owns 32 consecutive t's; lane l owns output dims [8l, 8l+8).
// ---------------------------------------------------------------------------
__global__ void __launch_bounds__(256, 4)
energy_ctx_kernel(const float* __restrict__ enc,
                  const float* __restrict__ mask) {
    __shared__ float smask[TPB + 2 * PAD];
    __shared__ float red_m[WPB], red_s[WPB];
    __shared__ __align__(16) float red_ctx[WPB][DIM];

    const int b   = blockIdx.x;
    const int ch  = blockIdx.y;
    const int tid = threadIdx.x;
    const int w   = tid >> 5;
    const int l   = tid & 31;
    const int t0  = ch * TPB;

    // register-resident slices
    const float4 uA = *(const float4*)(g_u + b * DIM + l * 8);
    const float4 uB = *(const float4*)(g_u + b * DIM + l * 8 + 4);
    const float  gl = (l < KS) ? g_g[b * KS + l] : 0.f;
    const float  cb = g_cb[b];

    for (int j = tid; j < TPB + 2 * PAD; j += 256) {
        int gt = t0 - PAD + j;
        smask[j] = (gt >= 0 && gt < T) ? mask[b * T + gt] : 0.f;
    }
    __syncthreads();

    const int tw0 = t0 + w * TPW;            // warp's first t
    float m = -INFINITY, s = 0.f;
    float cx[8] = {0.f, 0.f, 0.f, 0.f, 0.f, 0.f, 0.f, 0.f};

    const float* base = enc + ((size_t)tw0 * B + b) * DIM + l * 8;
    const size_t stride = (size_t)B * DIM;

    // rolling prefetch buffer, depth 2
    float4 pf0[2], pf1[2];
    pf0[0] = *(const float4*)(base);
    pf1[0] = *(const float4*)(base + 4);
    pf0[1] = *(const float4*)(base + stride);
    pf1[1] = *(const float4*)(base + stride + 4);

#pragma unroll 4
    for (int i = 0; i < TPW; i++) {
        const int slot = i & 1;
        const float4 a0 = pf0[slot], a1 = pf1[slot];
        if (i + 2 < TPW) {
            const float* np = base + (size_t)(i + 2) * stride;
            pf0[slot] = *(const float4*)np;
            pf1[slot] = *(const float4*)(np + 4);
        }
        const float msk = (l < KS) ? smask[w * TPW + i + l] : 0.f;

        float p;
        p = a0.x * uA.x;
        p = fmaf(a0.y, uA.y, p);
        p = fmaf(a0.z, uA.z, p);
        p = fmaf(a0.w, uA.w, p);
        p = fmaf(a1.x, uB.x, p);
        p = fmaf(a1.y, uB.y, p);
        p = fmaf(a1.z, uB.z, p);
        p = fmaf(a1.w, uB.w, p);
        p = fmaf(gl, msk, p);

#pragma unroll
        for (int off = 16; off > 0; off >>= 1)
            p += __shfl_xor_sync(0xffffffffu, p, off);
        p += cb;                              // uniform across warp

        if (l == 0) g_energ[b * T + tw0 + i] = p;

        if (p > m) {                          // warp-uniform branch
            const float sc = __expf(m - p);   // exp(-inf)=0 handles first row
            s = fmaf(s, sc, 1.f);
#pragma unroll
            for (int j = 0; j < 8; j++) cx[j] *= sc;
            m = p;
            cx[0] += a0.x; cx[1] += a0.y; cx[2] += a0.z; cx[3] += a0.w;
            cx[4] += a1.x; cx[5] += a1.y; cx[6] += a1.z; cx[7] += a1.w;
        } else {
            const float pe = __expf(p - m);
            s += pe;
            cx[0] = fmaf(pe, a0.x, cx[0]); cx[1] = fmaf(pe, a0.y, cx[1]);
            cx[2] = fmaf(pe, a0.z, cx[2]); cx[3] = fmaf(pe, a0.w, cx[3]);
            cx[4] = fmaf(pe, a1.x, cx[4]); cx[5] = fmaf(pe, a1.y, cx[5]);
            cx[6] = fmaf(pe, a1.z, cx[6]); cx[7] = fmaf(pe, a1.w, cx[7]);
        }
    }

    // ---- block epilogue: merge 8 warp partials ----
    if (l == 0) { red_m[w] = m; red_s[w] = s; }
    *(float4*)(&red_ctx[w][l * 8])     = *(float4*)(&cx[0]);
    *(float4*)(&red_ctx[w][l * 8 + 4]) = *(float4*)(&cx[4]);
    __syncthreads();

    float M = red_m[0];
#pragma unroll
    for (int j = 1; j < WPB; j++) M = fmaxf(M, red_m[j]);
    float S = 0.f, C = 0.f;
#pragma unroll
    for (int j = 0; j < WPB; j++) {
        const float wj = __expf(red_m[j] - M);
        S = fmaf(red_s[j], wj, S);
        C = fmaf(wj, red_ctx[j][tid], C);
    }

    const int pidx = b * NCH + ch;
    g_pctx[pidx * DIM + tid] = C;
    if (tid == 0) { g_pm[pidx] = M; g_ps[pidx] = S; }
}

// ---------------------------------------------------------------------------
// Kernel C (fused): per-batch combine of chunk partials + context write +
// attn epilogue. One block per batch.
// ---------------------------------------------------------------------------
__global__ void __launch_bounds__(256)
finish_kernel(float* __restrict__ out) {
    __shared__ float sm[NCH], ss[NCH];
    const int b = blockIdx.x, tid = threadIdx.x;
    if (tid < NCH) { sm[tid] = g_pm[b * NCH + tid]; ss[tid] = g_ps[b * NCH + tid]; }
    __syncthreads();

    float M = sm[0];
#pragma unroll
    for (int j = 1; j < NCH; j++) M = fmaxf(M, sm[j]);
    float S = 0.f;
#pragma unroll
    for (int j = 0; j < NCH; j++) S = fmaf(ss[j], __expf(sm[j] - M), S);
    const float invS = 1.0f / S;

    // context = sum_j exp(m_j - M) * pctx_j   (thread owns dim `tid`)
    float ctx = 0.f;
#pragma unroll
    for (int j = 0; j < NCH; j++)
        ctx = fmaf(__expf(sm[j] - M), g_pctx[(b * NCH + j) * DIM + tid], ctx);
    out[b * DIM + tid] = ctx * invS;

    // attn[b, :, 0] = exp(e - M) * invS, float4-vectorized (1024 f4 per batch)
    const float4* ep = (const float4*)(g_energ + (size_t)b * T);
    float4*       op = (float4*)(out + (size_t)B * DIM + (size_t)b * T);
#pragma unroll
    for (int i = tid; i < T / 4; i += 256) {
        float4 e = ep[i];
        float4 r;
        r.x = __expf(e.x - M) * invS;
        r.y = __expf(e.y - M) * invS;
        r.z = __expf(e.z - M) * invS;
        r.w = __expf(e.w - M) * invS;
        op[i] = r;
    }
}

// ---------------------------------------------------------------------------
extern "C" void kernel_launch(void* const* d_in, const int* in_sizes, int n_in,
                              void* d_out, int out_size) {
    const float* q     = (const float*)d_in[0];  // (1,64,256)
    const float* enc   = (const float*)d_in[1];  // (4096,64,256)
    const float* mask  = (const float*)d_in[2];  // (64,4096,1)
    const float* Ww    = (const float*)d_in[3];  // (256,256)
    const float* Lw    = (const float*)d_in[4];  // (256,32)
    const float* convw = (const float*)d_in[5];  // (32,1,31)
    const float* convb = (const float*)d_in[6];  // (32,)
    float* out = (float*)d_out;                  // context(16384) ++ attn(262144)

    prep_kernel<<<B, 256>>>(q, Ww, Lw, convw, convb);
    dim3 gridB(B, NCH);
    energy_ctx_kernel<<<gridB, 256>>>(enc, mask);
    finish_kernel<<<B, 256>>>(out);
}

// round 6
// speedup vs baseline: 2.3976x; 1.4045x over previous
#include <cuda_runtime.h>
#include <math.h>

#define B    64
#define T    4096
#define DIM  256
#define NLOC 32
#define KS   31
#define PAD  15
#define TPW  32             // rows per warp
#define WPB  8              // warps per block
#define TPB  (TPW * WPB)    // 256 t per block
#define NCH  (T / TPB)      // 16 chunks per batch -> 1024 blocks

// -------- scratch (static device globals; no allocation allowed) ----------
__device__ float g_u[B * DIM];            // W^T q per batch
__device__ float g_g[B * KS];             // collapsed conv kernel per batch
__device__ float g_cb[B];                 // collapsed conv bias per batch
__device__ float g_energ[B * T];          // raw energies
__device__ float g_pm[B * NCH];           // per-block running max
__device__ float g_ps[B * NCH];           // per-block exp-sum
__device__ float g_pctx[B * NCH * DIM];   // per-block unnormalized context

// ---------------------------------------------------------------------------
// Kernel A: prep, parallelized. grid = (B, 9).
//   chunk c in [0,8): u[b, c*32 .. c*32+32) = W^T q slice
//   chunk 8:          v = L^T q ; g = conv_w^T v ; cb = conv_b . v
// Thread map inside a chunk: tid = eg*32 + lane; each thread accumulates 32
// e-terms with coalesced loads; 8 partials reduced via shared memory.
// ---------------------------------------------------------------------------
__global__ void __launch_bounds__(256)
prep_kernel(const float* __restrict__ q,
            const float* __restrict__ Ww,
            const float* __restrict__ Lw,
            const float* __restrict__ convw,
            const float* __restrict__ convb) {
    __shared__ float sq[DIM];
    __shared__ float part[8][32];
    __shared__ float sv[NLOC];

    const int b   = blockIdx.x;
    const int c   = blockIdx.y;
    const int tid = threadIdx.x;
    const int ln  = tid & 31;
    const int eg  = tid >> 5;

    sq[tid] = q[b * DIM + tid];
    __syncthreads();

    if (c < 8) {
        // u slice: d = c*32 + ln ; sum over e in [eg*32, eg*32+32)
        const float* wp = Ww + (size_t)(eg * 32) * DIM + c * 32 + ln;
        float acc = 0.f;
#pragma unroll
        for (int e = 0; e < 32; e++)
            acc = fmaf(wp[(size_t)e * DIM], sq[eg * 32 + e], acc);
        part[eg][ln] = acc;
        __syncthreads();
        if (tid < 32) {
            float u = part[0][tid];
#pragma unroll
            for (int j = 1; j < 8; j++) u += part[j][tid];
            g_u[b * DIM + c * 32 + tid] = u;
        }
    } else {
        // v[cl] = sum_e Lw[e*NLOC + cl] * q[e]
        const float* lp = Lw + (size_t)(eg * 32) * NLOC + ln;
        float acc = 0.f;
#pragma unroll
        for (int e = 0; e < 32; e++)
            acc = fmaf(lp[(size_t)e * NLOC], sq[eg * 32 + e], acc);
        part[eg][ln] = acc;
        __syncthreads();
        if (tid < 32) {
            float v = part[0][tid];
#pragma unroll
            for (int j = 1; j < 8; j++) v += part[j][tid];
            sv[tid] = v;
        }
        __syncthreads();
        if (tid < KS) {
            float gg = 0.f;
#pragma unroll
            for (int cc = 0; cc < NLOC; cc++)
                gg = fmaf(convw[cc * KS + tid], sv[cc], gg);
            g_g[b * KS + tid] = gg;
        }
        if (tid == 0) {
            float cb = 0.f;
#pragma unroll
            for (int cc = 0; cc < NLOC; cc++) cb = fmaf(convb[cc], sv[cc], cb);
            g_cb[b] = cb;
        }
    }
}

// ---------------------------------------------------------------------------
// Kernel B: HBM-bound pass, warp-autonomous hot loop, prefetch depth 2.
// Each warp owns 32 consecutive t's; lane l owns output dims [8l, 8l+8).
// ---------------------------------------------------------------------------
__global__ void __launch_bounds__(256, 4)
energy_ctx_kernel(const float* __restrict__ enc,
                  const float* __restrict__ mask) {
    __shared__ float smask[TPB + 2 * PAD];
    __shared__ float red_m[WPB], red_s[WPB];
    __shared__ __align__(16) float red_ctx[WPB][DIM];

    const int b   = blockIdx.x;
    const int ch  = blockIdx.y;
    const int tid = threadIdx.x;
    const int w   = tid >> 5;
    const int l   = tid & 31;
    const int t0  = ch * TPB;

    const float4 uA = *(const float4*)(g_u + b * DIM + l * 8);
    const float4 uB = *(const float4*)(g_u + b * DIM + l * 8 + 4);
    const float  gl = (l < KS) ? g_g[b * KS + l] : 0.f;
    const float  cb = g_cb[b];

    for (int j = tid; j < TPB + 2 * PAD; j += 256) {
        int gt = t0 - PAD + j;
        smask[j] = (gt >= 0 && gt < T) ? mask[b * T + gt] : 0.f;
    }
    __syncthreads();

    const int tw0 = t0 + w * TPW;
    float m = -INFINITY, s = 0.f;
    float cx[8] = {0.f, 0.f, 0.f, 0.f, 0.f, 0.f, 0.f, 0.f};

    const float* base = enc + ((size_t)tw0 * B + b) * DIM + l * 8;
    const size_t stride = (size_t)B * DIM;

    float4 pf0[2], pf1[2];
    pf0[0] = *(const float4*)(base);
    pf1[0] = *(const float4*)(base + 4);
    pf0[1] = *(const float4*)(base + stride);
    pf1[1] = *(const float4*)(base + stride + 4);

#pragma unroll 4
    for (int i = 0; i < TPW; i++) {
        const int slot = i & 1;
        const float4 a0 = pf0[slot], a1 = pf1[slot];
        if (i + 2 < TPW) {
            const float* np = base + (size_t)(i + 2) * stride;
            pf0[slot] = *(const float4*)np;
            pf1[slot] = *(const float4*)(np + 4);
        }
        const float msk = (l < KS) ? smask[w * TPW + i + l] : 0.f;

        float p;
        p = a0.x * uA.x;
        p = fmaf(a0.y, uA.y, p);
        p = fmaf(a0.z, uA.z, p);
        p = fmaf(a0.w, uA.w, p);
        p = fmaf(a1.x, uB.x, p);
        p = fmaf(a1.y, uB.y, p);
        p = fmaf(a1.z, uB.z, p);
        p = fmaf(a1.w, uB.w, p);
        p = fmaf(gl, msk, p);

#pragma unroll
        for (int off = 16; off > 0; off >>= 1)
            p += __shfl_xor_sync(0xffffffffu, p, off);
        p += cb;

        if (l == 0) g_energ[b * T + tw0 + i] = p;

        if (p > m) {
            const float sc = __expf(m - p);
            s = fmaf(s, sc, 1.f);
#pragma unroll
            for (int j = 0; j < 8; j++) cx[j] *= sc;
            m = p;
            cx[0] += a0.x; cx[1] += a0.y; cx[2] += a0.z; cx[3] += a0.w;
            cx[4] += a1.x; cx[5] += a1.y; cx[6] += a1.z; cx[7] += a1.w;
        } else {
            const float pe = __expf(p - m);
            s += pe;
            cx[0] = fmaf(pe, a0.x, cx[0]); cx[1] = fmaf(pe, a0.y, cx[1]);
            cx[2] = fmaf(pe, a0.z, cx[2]); cx[3] = fmaf(pe, a0.w, cx[3]);
            cx[4] = fmaf(pe, a1.x, cx[4]); cx[5] = fmaf(pe, a1.y, cx[5]);
            cx[6] = fmaf(pe, a1.z, cx[6]); cx[7] = fmaf(pe, a1.w, cx[7]);
        }
    }

    if (l == 0) { red_m[w] = m; red_s[w] = s; }
    *(float4*)(&red_ctx[w][l * 8])     = *(float4*)(&cx[0]);
    *(float4*)(&red_ctx[w][l * 8 + 4]) = *(float4*)(&cx[4]);
    __syncthreads();

    float M = red_m[0];
#pragma unroll
    for (int j = 1; j < WPB; j++) M = fmaxf(M, red_m[j]);
    float S = 0.f, C = 0.f;
#pragma unroll
    for (int j = 0; j < WPB; j++) {
        const float wj = __expf(red_m[j] - M);
        S = fmaf(red_s[j], wj, S);
        C = fmaf(wj, red_ctx[j][tid], C);
    }

    const int pidx = b * NCH + ch;
    g_pctx[pidx * DIM + tid] = C;
    if (tid == 0) { g_pm[pidx] = M; g_ps[pidx] = S; }
}

// ---------------------------------------------------------------------------
// Kernel C (fused, widened): grid (B, 4). Every block recomputes M,S from the
// 16 chunk partials (cheap); slice 0 writes context; all slices write a
// quarter of the batch's attn row.
// ---------------------------------------------------------------------------
__global__ void __launch_bounds__(256)
finish_kernel(float* __restrict__ out) {
    __shared__ float sm[NCH], ss[NCH];
    const int b = blockIdx.x, sl = blockIdx.y, tid = threadIdx.x;
    if (tid < NCH) { sm[tid] = g_pm[b * NCH + tid]; ss[tid] = g_ps[b * NCH + tid]; }
    __syncthreads();

    float M = sm[0];
#pragma unroll
    for (int j = 1; j < NCH; j++) M = fmaxf(M, sm[j]);
    float S = 0.f;
#pragma unroll
    for (int j = 0; j < NCH; j++) S = fmaf(ss[j], __expf(sm[j] - M), S);
    const float invS = 1.0f / S;

    if (sl == 0) {
        float ctx = 0.f;
#pragma unroll
        for (int j = 0; j < NCH; j++)
            ctx = fmaf(__expf(sm[j] - M), g_pctx[(b * NCH + j) * DIM + tid], ctx);
        out[b * DIM + tid] = ctx * invS;
    }

    // attn quarter: 256 float4 per slice
    const float4* ep = (const float4*)(g_energ + (size_t)b * T) + sl * 256;
    float4*       op = (float4*)(out + (size_t)B * DIM + (size_t)b * T) + sl * 256;
    float4 e = ep[tid];
    float4 r;
    r.x = __expf(e.x - M) * invS;
    r.y = __expf(e.y - M) * invS;
    r.z = __expf(e.z - M) * invS;
    r.w = __expf(e.w - M) * invS;
    op[tid] = r;
}

// ---------------------------------------------------------------------------
extern "C" void kernel_launch(void* const* d_in, const int* in_sizes, int n_in,
                              void* d_out, int out_size) {
    const float* q     = (const float*)d_in[0];  // (1,64,256)
    const float* enc   = (const float*)d_in[1];  // (4096,64,256)
    const float* mask  = (const float*)d_in[2];  // (64,4096,1)
    const float* Ww    = (const float*)d_in[3];  // (256,256)
    const float* Lw    = (const float*)d_in[4];  // (256,32)
    const float* convw = (const float*)d_in[5];  // (32,1,31)
    const float* convb = (const float*)d_in[6];  // (32,)
    float* out = (float*)d_out;                  // context(16384) ++ attn(262144)

    dim3 gridA(B, 9);
    prep_kernel<<<gridA, 256>>>(q, Ww, Lw, convw, convb);
    dim3 gridB(B, NCH);
    energy_ctx_kernel<<<gridB, 256>>>(enc, mask);
    dim3 gridC(B, 4);
    finish_kernel<<<gridC, 256>>>(out);
}